// round 4
// baseline (speedup 1.0000x reference)
#include <cuda_runtime.h>
#include <math_constants.h>

// Problem constants
#define SEQ   1024
#define BATCH 8
#define EMB   1024
#define NH    16
#define HD    64
#define MROWS (SEQ*BATCH)        // 8192
#define NHEADS_TOT (BATCH*NH)    // 128

// Scratch (device globals; allocation-free)
__device__ float g_Q[NHEADS_TOT * SEQ * HD];  // 32 MB, [n][s][d], pre-scaled by 1/8
__device__ float g_K[NHEADS_TOT * SEQ * HD];
__device__ float g_V[NHEADS_TOT * SEQ * HD];
__device__ float g_C[MROWS * EMB];            // ctx in [s,b,e] layout

// ---------------------------------------------------------------------------
// SGEMM: C[M,N] = A[M,1024] @ B[N,1024]^T + bias[N]
// BM=BN=128, BK=8, 256 threads, 8x8 per thread.
// MODE 0: A = X (d_in[0]); epilogue scatters into g_Q/g_K/g_V (QKV proj, N=3072)
// MODE 1: A = g_C;        epilogue writes Cout[m*1024+n]       (out proj, N=1024)
// ---------------------------------------------------------------------------
template<int MODE>
__global__ __launch_bounds__(256) void sgemm_kernel(
    const float* __restrict__ A, const float* __restrict__ B,
    const float* __restrict__ bias, float* __restrict__ Cout)
{
    __shared__ float As[8][128];
    __shared__ float Bs[8][128];

    const int tid = threadIdx.x;
    const int m0 = blockIdx.y * 128;
    const int n0 = blockIdx.x * 128;

    const float* Asrc = (MODE == 0) ? A : g_C;

    const int lr = tid >> 1;         // 0..127
    const int lk = (tid & 1) << 2;   // 0 or 4
    const float* Ag = Asrc + (size_t)(m0 + lr) * 1024 + lk;
    const float* Bg = B    + (size_t)(n0 + lr) * 1024 + lk;

    const int tx = tid & 15;
    const int ty = tid >> 4;

    float acc[8][8];
    #pragma unroll
    for (int i = 0; i < 8; i++)
        #pragma unroll
        for (int j = 0; j < 8; j++) acc[i][j] = 0.0f;

    for (int k0 = 0; k0 < 1024; k0 += 8) {
        float4 a4 = *(const float4*)(Ag + k0);
        float4 b4 = *(const float4*)(Bg + k0);
        As[lk+0][lr] = a4.x; As[lk+1][lr] = a4.y;
        As[lk+2][lr] = a4.z; As[lk+3][lr] = a4.w;
        Bs[lk+0][lr] = b4.x; Bs[lk+1][lr] = b4.y;
        Bs[lk+2][lr] = b4.z; Bs[lk+3][lr] = b4.w;
        __syncthreads();

        #pragma unroll
        for (int kk = 0; kk < 8; kk++) {
            float ar[8], br[8];
            *(float4*)(ar)     = *(const float4*)(&As[kk][ty*8]);
            *(float4*)(ar + 4) = *(const float4*)(&As[kk][ty*8 + 4]);
            *(float4*)(br)     = *(const float4*)(&Bs[kk][tx*8]);
            *(float4*)(br + 4) = *(const float4*)(&Bs[kk][tx*8 + 4]);
            #pragma unroll
            for (int i = 0; i < 8; i++)
                #pragma unroll
                for (int j = 0; j < 8; j++)
                    acc[i][j] = fmaf(ar[i], br[j], acc[i][j]);
        }
        __syncthreads();
    }

    // Epilogue
    #pragma unroll
    for (int i = 0; i < 8; i++) {
        const int m = m0 + ty*8 + i;
        #pragma unroll
        for (int j = 0; j < 8; j++) {
            const int n = n0 + tx*8 + j;
            float v = acc[i][j] + bias[n];
            if (MODE == 0) {
                // m -> (s, b); n -> (h, which, d)
                const int s = m >> 3;        // m / BATCH
                const int b = m & 7;
                const int h = n / 192;
                const int c = n - h * 192;
                const int w = c >> 6;        // 0=Q,1=K,2=V
                const int d = c & 63;
                const size_t idx = ((size_t)(b * NH + h) * SEQ + s) * HD + d;
                if (w == 0)      g_Q[idx] = v * 0.125f;   // 1/sqrt(64)
                else if (w == 1) g_K[idx] = v;
                else             g_V[idx] = v;
            } else {
                Cout[(size_t)m * 1024 + n] = v;
            }
        }
    }
}

// ---------------------------------------------------------------------------
// Flash attention: grid (16 q-tiles, 128 heads), 256 threads.
// Phase A (per K tile): thread owns q=tid>>2, 16 interleaved k's; computes
//   scores, online-softmax stats (shfl over the 4 lanes sharing a row),
//   writes P into Ss and per-row rescale factor into sscale.
// Phase B: thread owns 4 rows x 4 cols of O; rescale + P@V accumulate.
// Pads: Ks/Vs stride 68 (float4-aligned, conflict-free for the access
// patterns used), Ss stride 65.
// ---------------------------------------------------------------------------
#define KV_PAD 68
#define SS_PAD 65
#define ATTN_SMEM ((2*64*KV_PAD + 64*SS_PAD + 128) * 4)

__global__ __launch_bounds__(256) void attn_kernel()
{
    extern __shared__ float sh[];
    float* Ks     = sh;
    float* Vs     = Ks + 64 * KV_PAD;
    float* Ss     = Vs + 64 * KV_PAD;
    float* sscale = Ss + 64 * SS_PAD;
    float* sl     = sscale + 64;

    const int tid = threadIdx.x;
    const int n   = blockIdx.y;             // head index (b*16+h)
    const int qt  = blockIdx.x;             // query tile

    const float* Qg = g_Q + ((size_t)n * SEQ + qt * 64) * HD;
    const float* Kg = g_K + (size_t)n * SEQ * HD;
    const float* Vg = g_V + (size_t)n * SEQ * HD;

    // Phase-A identity
    const int q  = tid >> 2;                // 0..63
    const int kg = tid & 3;                 // k lane group
    // Phase-B identity
    const int qb = (tid >> 4) * 4;          // row block base
    const int c0 = (tid & 15) * 4;          // col base

    // Cache this thread's Q row (already scaled by 1/8)
    float4 qv[16];
    const float4* qrow = (const float4*)(Qg + q * HD);
    #pragma unroll
    for (int i = 0; i < 16; i++) qv[i] = qrow[i];

    float mrun = -CUDART_INF_F;
    float lrun = 0.0f;
    float4 o[4];
    #pragma unroll
    for (int i = 0; i < 4; i++) o[i] = make_float4(0.f, 0.f, 0.f, 0.f);

    for (int kt = 0; kt < 16; kt++) {
        // Load K,V 64x64 tile
        #pragma unroll
        for (int it = 0; it < 4; it++) {
            const int i4 = tid + it * 256;
            const int r  = i4 >> 4;
            const int c4 = (i4 & 15) << 2;
            const float4 kv = *(const float4*)(Kg + (size_t)(kt*64 + r) * HD + c4);
            const float4 vv = *(const float4*)(Vg + (size_t)(kt*64 + r) * HD + c4);
            float* kd = &Ks[r * KV_PAD + c4];
            kd[0] = kv.x; kd[1] = kv.y; kd[2] = kv.z; kd[3] = kv.w;
            float* vd = &Vs[r * KV_PAD + c4];
            vd[0] = vv.x; vd[1] = vv.y; vd[2] = vv.z; vd[3] = vv.w;
        }
        __syncthreads();

        // ---- Phase A: scores + online softmax ----
        float sc[16];
        #pragma unroll
        for (int kk = 0; kk < 16; kk++) {
            const int k = kg + (kk << 2);
            const float4* kr = (const float4*)(&Ks[k * KV_PAD]);
            float a = 0.f;
            #pragma unroll
            for (int d4 = 0; d4 < 16; d4++) {
                const float4 kvv = kr[d4];
                a = fmaf(qv[d4].x, kvv.x, a);
                a = fmaf(qv[d4].y, kvv.y, a);
                a = fmaf(qv[d4].z, kvv.z, a);
                a = fmaf(qv[d4].w, kvv.w, a);
            }
            sc[kk] = a;
        }
        // row max across my 16 + the 3 sibling lanes
        float rmax = sc[0];
        #pragma unroll
        for (int kk = 1; kk < 16; kk++) rmax = fmaxf(rmax, sc[kk]);
        rmax = fmaxf(rmax, __shfl_xor_sync(0xffffffffu, rmax, 1));
        rmax = fmaxf(rmax, __shfl_xor_sync(0xffffffffu, rmax, 2));

        const float mnew = fmaxf(mrun, rmax);
        const float scalef = __expf(mrun - mnew);   // 0 on first tile
        float psum = 0.f;
        #pragma unroll
        for (int kk = 0; kk < 16; kk++) {
            const float p = __expf(sc[kk] - mnew);
            psum += p;
            Ss[q * SS_PAD + (kg + (kk << 2))] = p;
        }
        psum += __shfl_xor_sync(0xffffffffu, psum, 1);
        psum += __shfl_xor_sync(0xffffffffu, psum, 2);
        lrun = lrun * scalef + psum;
        mrun = mnew;
        if (kg == 0) sscale[q] = scalef;
        __syncthreads();

        // ---- Phase B: O = O*scale + P @ V ----
        #pragma unroll
        for (int i = 0; i < 4; i++) {
            const float s2 = sscale[qb + i];
            o[i].x *= s2; o[i].y *= s2; o[i].z *= s2; o[i].w *= s2;
        }
        #pragma unroll 8
        for (int k = 0; k < 64; k++) {
            const float4 vvv = *(const float4*)(&Vs[k * KV_PAD + c0]);
            #pragma unroll
            for (int i = 0; i < 4; i++) {
                const float p = Ss[(qb + i) * SS_PAD + k];
                o[i].x = fmaf(p, vvv.x, o[i].x);
                o[i].y = fmaf(p, vvv.y, o[i].y);
                o[i].z = fmaf(p, vvv.z, o[i].z);
                o[i].w = fmaf(p, vvv.w, o[i].w);
            }
        }
        __syncthreads();
    }

    // publish row sums, then normalize + write out
    if (kg == 0) sl[q] = lrun;
    __syncthreads();

    const int b = n >> 4;    // batch
    const int h = n & 15;    // head
    #pragma unroll
    for (int i = 0; i < 4; i++) {
        const float inv = 1.0f / sl[qb + i];
        const int sgl = qt * 64 + qb + i;
        float4 r;
        r.x = o[i].x * inv; r.y = o[i].y * inv;
        r.z = o[i].z * inv; r.w = o[i].w * inv;
        *(float4*)(&g_C[((size_t)sgl * BATCH + b) * EMB + h * HD + c0]) = r;
    }
}

// ---------------------------------------------------------------------------
extern "C" void kernel_launch(void* const* d_in, const int* in_sizes, int n_in,
                              void* d_out, int out_size)
{
    const float* X  = (const float*)d_in[0];  // query [S,B,E]
    const float* Wq = (const float*)d_in[3];  // in_proj_w [3E,E]
    const float* bq = (const float*)d_in[4];  // in_proj_b [3E]
    const float* Wo = (const float*)d_in[5];  // out_proj_w [E,E]
    const float* bo = (const float*)d_in[6];  // out_proj_b [E]
    float* out = (float*)d_out;

    cudaFuncSetAttribute(attn_kernel,
                         cudaFuncAttributeMaxDynamicSharedMemorySize, ATTN_SMEM);

    // 1) QKV projection + scatter
    sgemm_kernel<0><<<dim3(3072/128, MROWS/128), 256>>>(X, Wq, bq, nullptr);
    // 2) Attention
    attn_kernel<<<dim3(SEQ/64, NHEADS_TOT), 256, ATTN_SMEM>>>();
    // 3) Output projection
    sgemm_kernel<1><<<dim3(1024/128, MROWS/128), 256>>>(nullptr, Wo, bo, out);
}

// round 7
// speedup vs baseline: 1.2080x; 1.2080x over previous
#include <cuda_runtime.h>
#include <math_constants.h>
#include <cstdint>

// Problem constants
#define SEQ   1024
#define BATCH 8
#define EMB   1024
#define NH    16
#define HD    64
#define MROWS (SEQ*BATCH)        // 8192
#define NHEADS_TOT (BATCH*NH)    // 128

// ---------------------------------------------------------------------------
// Scratch (device globals; allocation-free)
// ---------------------------------------------------------------------------
__device__ float g_Q[NHEADS_TOT * SEQ * HD];   // [n][s][d], pre-scaled by 1/8
__device__ float g_K[NHEADS_TOT * SEQ * HD];
__device__ float g_V[NHEADS_TOT * SEQ * HD];
__device__ float g_Xhi[MROWS * EMB];
__device__ float g_Xlo[MROWS * EMB];
__device__ float g_Wqhi[3 * EMB * EMB];
__device__ float g_Wqlo[3 * EMB * EMB];
__device__ float g_Wohi[EMB * EMB];
__device__ float g_Wolo[EMB * EMB];
__device__ float g_Chi[MROWS * EMB];           // ctx hi split, [s,b,e]
__device__ float g_Clo[MROWS * EMB];           // ctx lo split

// ---------------------------------------------------------------------------
// Helpers (sm_103 plain: mma.sync + cp.async only; NO tcgen05 anywhere)
// ---------------------------------------------------------------------------
__device__ __forceinline__ uint32_t smem_u32(const void* p) {
    uint32_t a;
    asm("{ .reg .u64 t; cvta.to.shared.u64 t, %1; cvt.u32.u64 %0, t; }"
        : "=r"(a) : "l"(p));
    return a;
}

__device__ __forceinline__ void cp16(uint32_t dst, const float* src) {
    asm volatile("cp.async.cg.shared.global [%0], [%1], 16;" :: "r"(dst), "l"(src));
}

__device__ __forceinline__ float tf32_rna(float x) {
    uint32_t u;
    asm("cvt.rna.tf32.f32 %0, %1;" : "=r"(u) : "f"(x));
    return __uint_as_float(u);
}

// D += A(16x8,row) * B(8x8,col) ; tf32 operands, f32 accum
__device__ __forceinline__ void mma8(float* c, const uint32_t* a, const uint32_t* b) {
    asm volatile(
        "mma.sync.aligned.m16n8k8.row.col.f32.tf32.tf32.f32 "
        "{%0,%1,%2,%3}, {%4,%5,%6,%7}, {%8,%9}, {%0,%1,%2,%3};"
        : "+f"(c[0]), "+f"(c[1]), "+f"(c[2]), "+f"(c[3])
        : "r"(a[0]), "r"(a[1]), "r"(a[2]), "r"(a[3]), "r"(b[0]), "r"(b[1]));
}

// ---------------------------------------------------------------------------
// Split kernel: x -> (hi = tf32(x), lo = tf32(x - hi))
// ---------------------------------------------------------------------------
__global__ __launch_bounds__(256) void split_kernel(
    const float4* __restrict__ src, float4* __restrict__ hi,
    float4* __restrict__ lo, int n4)
{
    int i = blockIdx.x * 256 + threadIdx.x;
    if (i >= n4) return;
    float4 x = src[i];
    float4 h, l;
    h.x = tf32_rna(x.x); l.x = tf32_rna(x.x - h.x);
    h.y = tf32_rna(x.y); l.y = tf32_rna(x.y - h.y);
    h.z = tf32_rna(x.z); l.z = tf32_rna(x.z - h.z);
    h.w = tf32_rna(x.w); l.w = tf32_rna(x.w - h.w);
    hi[i] = h; lo[i] = l;
}

// ---------------------------------------------------------------------------
// tf32x3 GEMM via mma.sync: C[M,N] = A[M,1024] @ B[N,1024]^T + bias[N]
// Block tile 128x128, BK=32 floats, 2-stage cp.async pipeline, 256 threads.
// 8 warps in 2(m)x4(n); warp tile 64x32 = 4x4 m16n8k8 tiles.
// 3 MMAs per tile per k8: Ahi*Bhi + Ahi*Blo + Alo*Bhi.
// MODE 0: QKV proj — scatter into g_Q/g_K/g_V.  MODE 1: out proj — Cout+bias.
// ---------------------------------------------------------------------------
#define BKF   32                  // K floats per chunk
#define ASTR  36                  // smem row stride (conflict-free: 4r+c distinct)
#define T_OFF (128*ASTR)          // floats per tensor tile in a stage
#define STAGE_F (4*T_OFF)
#define G_SMEM (2*STAGE_F*4)      // 147456 bytes
#define NCHUNK (1024/BKF)         // 32

template<int MODE>
__global__ __launch_bounds__(256, 1)
void tc_gemm(const float* __restrict__ Ahi, const float* __restrict__ Alo,
             const float* __restrict__ Bhi, const float* __restrict__ Blo,
             const float* __restrict__ bias, float* __restrict__ Cout)
{
    extern __shared__ float sm[];
    const int tid  = threadIdx.x;
    const int wid  = tid >> 5;
    const int lane = tid & 31;
    const int m0 = blockIdx.y * 128;
    const int n0 = blockIdx.x * 128;
    const int warp_m = (wid & 1) * 64;
    const int warp_n = (wid >> 1) * 32;
    const int lr = lane >> 2;      // fragment row within 8
    const int lc = lane & 3;       // fragment col within 4

    float acc[4][4][4];
    #pragma unroll
    for (int mt = 0; mt < 4; mt++)
        #pragma unroll
        for (int nt = 0; nt < 4; nt++)
            #pragma unroll
            for (int r = 0; r < 4; r++) acc[mt][nt][r] = 0.0f;

    const uint32_t smb = smem_u32(sm);

    // chunk loader: 4 tensors x 128 rows x 8 quads; 4 cp16 per thread per tensor
    auto load_chunk = [&](int st, int k0) {
        const uint32_t sb = smb + (uint32_t)st * (STAGE_F * 4);
        #pragma unroll
        for (int i = 0; i < 4; i++) {
            const int idx = tid + i * 256;
            const int r = idx >> 3, q = idx & 7;
            const uint32_t o = (uint32_t)r * (ASTR * 4) + (uint32_t)q * 16;
            const size_t ga = (size_t)(m0 + r) * 1024 + k0 + q * 4;
            const size_t gb = (size_t)(n0 + r) * 1024 + k0 + q * 4;
            cp16(sb + 0 * (T_OFF * 4) + o, Ahi + ga);
            cp16(sb + 1 * (T_OFF * 4) + o, Alo + ga);
            cp16(sb + 2 * (T_OFF * 4) + o, Bhi + gb);
            cp16(sb + 3 * (T_OFF * 4) + o, Blo + gb);
        }
        asm volatile("cp.async.commit_group;" ::: "memory");
    };

    load_chunk(0, 0);
    load_chunk(1, BKF);

    for (int c = 0; c < NCHUNK; c++) {
        if (c < NCHUNK - 1) asm volatile("cp.async.wait_group 1;" ::: "memory");
        else                asm volatile("cp.async.wait_group 0;" ::: "memory");
        __syncthreads();

        const float* As_hi = sm + (c & 1) * STAGE_F;
        const float* As_lo = As_hi + T_OFF;
        const float* Bs_hi = As_hi + 2 * T_OFF;
        const float* Bs_lo = As_hi + 3 * T_OFF;

        #pragma unroll
        for (int kk = 0; kk < BKF; kk += 8) {
            uint32_t ah[4][4], al[4][4], bh[4][2], bl[4][2];
            #pragma unroll
            for (int mt = 0; mt < 4; mt++) {
                const int r = warp_m + mt * 16 + lr;
                const float* p  = As_hi + r * ASTR + kk + lc;
                const float* pl = As_lo + r * ASTR + kk + lc;
                ah[mt][0] = __float_as_uint(p[0]);
                ah[mt][1] = __float_as_uint(p[8 * ASTR]);
                ah[mt][2] = __float_as_uint(p[4]);
                ah[mt][3] = __float_as_uint(p[8 * ASTR + 4]);
                al[mt][0] = __float_as_uint(pl[0]);
                al[mt][1] = __float_as_uint(pl[8 * ASTR]);
                al[mt][2] = __float_as_uint(pl[4]);
                al[mt][3] = __float_as_uint(pl[8 * ASTR + 4]);
            }
            #pragma unroll
            for (int nt = 0; nt < 4; nt++) {
                const int r = warp_n + nt * 8 + lr;
                const float* p  = Bs_hi + r * ASTR + kk + lc;
                const float* pl = Bs_lo + r * ASTR + kk + lc;
                bh[nt][0] = __float_as_uint(p[0]);
                bh[nt][1] = __float_as_uint(p[4]);
                bl[nt][0] = __float_as_uint(pl[0]);
                bl[nt][1] = __float_as_uint(pl[4]);
            }
            #pragma unroll
            for (int mt = 0; mt < 4; mt++)
                #pragma unroll
                for (int nt = 0; nt < 4; nt++) {
                    mma8(acc[mt][nt], ah[mt], bh[nt]);
                    mma8(acc[mt][nt], ah[mt], bl[nt]);
                    mma8(acc[mt][nt], al[mt], bh[nt]);
                }
        }
        __syncthreads();
        if (c + 2 < NCHUNK) load_chunk(c & 1, (c + 2) * BKF);
    }

    // ---- Epilogue: direct global stores (pairs of consecutive n) ----
    #pragma unroll
    for (int mt = 0; mt < 4; mt++) {
        #pragma unroll
        for (int nt = 0; nt < 4; nt++) {
            const int gm = m0 + warp_m + mt * 16 + lr;
            const int gn = n0 + warp_n + nt * 8 + lc * 2;
            #pragma unroll
            for (int half = 0; half < 2; half++) {
                const int m = gm + half * 8;
                const float v0 = acc[mt][nt][half * 2 + 0] + __ldg(&bias[gn]);
                const float v1 = acc[mt][nt][half * 2 + 1] + __ldg(&bias[gn + 1]);
                if (MODE == 0) {
                    const int s = m >> 3;            // m / BATCH
                    const int b = m & 7;
                    const int h = gn / 192;
                    const int cc = gn - h * 192;
                    const int w = cc >> 6;           // 0=Q,1=K,2=V (pair never straddles)
                    const int d = cc & 63;
                    const size_t idx = ((size_t)(b * NH + h) * SEQ + s) * HD + d;
                    if (w == 0)      { g_Q[idx] = v0 * 0.125f; g_Q[idx + 1] = v1 * 0.125f; }
                    else if (w == 1) { g_K[idx] = v0;          g_K[idx + 1] = v1; }
                    else             { g_V[idx] = v0;          g_V[idx + 1] = v1; }
                } else {
                    Cout[(size_t)m * 1024 + gn]     = v0;
                    Cout[(size_t)m * 1024 + gn + 1] = v1;
                }
            }
        }
    }
}

// ---------------------------------------------------------------------------
// Flash attention (proven-correct SIMT path): grid (16 q-tiles, 128 heads).
// Epilogue writes tf32 hi/lo splits of the context for the out-proj GEMM.
// ---------------------------------------------------------------------------
#define KV_PAD 68
#define SS_PAD 65
#define ATTN_SMEM ((2*64*KV_PAD + 64*SS_PAD + 128) * 4)

__global__ __launch_bounds__(256) void attn_kernel()
{
    extern __shared__ float sh[];
    float* Ks     = sh;
    float* Vs     = Ks + 64 * KV_PAD;
    float* Ss     = Vs + 64 * KV_PAD;
    float* sscale = Ss + 64 * SS_PAD;
    float* sl     = sscale + 64;

    const int tid = threadIdx.x;
    const int n   = blockIdx.y;             // head index (b*16+h)
    const int qt  = blockIdx.x;             // query tile

    const float* Qg = g_Q + ((size_t)n * SEQ + qt * 64) * HD;
    const float* Kg = g_K + (size_t)n * SEQ * HD;
    const float* Vg = g_V + (size_t)n * SEQ * HD;

    const int q  = tid >> 2;
    const int kg = tid & 3;
    const int qb = (tid >> 4) * 4;
    const int c0 = (tid & 15) * 4;

    float4 qv[16];
    const float4* qrow = (const float4*)(Qg + q * HD);
    #pragma unroll
    for (int i = 0; i < 16; i++) qv[i] = qrow[i];

    float mrun = -CUDART_INF_F;
    float lrun = 0.0f;
    float4 o[4];
    #pragma unroll
    for (int i = 0; i < 4; i++) o[i] = make_float4(0.f, 0.f, 0.f, 0.f);

    for (int kt = 0; kt < 16; kt++) {
        #pragma unroll
        for (int it = 0; it < 4; it++) {
            const int i4 = tid + it * 256;
            const int r  = i4 >> 4;
            const int c4 = (i4 & 15) << 2;
            const float4 kv = *(const float4*)(Kg + (size_t)(kt*64 + r) * HD + c4);
            const float4 vv = *(const float4*)(Vg + (size_t)(kt*64 + r) * HD + c4);
            float* kd = &Ks[r * KV_PAD + c4];
            kd[0] = kv.x; kd[1] = kv.y; kd[2] = kv.z; kd[3] = kv.w;
            float* vd = &Vs[r * KV_PAD + c4];
            vd[0] = vv.x; vd[1] = vv.y; vd[2] = vv.z; vd[3] = vv.w;
        }
        __syncthreads();

        float sc[16];
        #pragma unroll
        for (int kk = 0; kk < 16; kk++) {
            const int k = kg + (kk << 2);
            const float4* kr = (const float4*)(&Ks[k * KV_PAD]);
            float a = 0.f;
            #pragma unroll
            for (int d4 = 0; d4 < 16; d4++) {
                const float4 kvv = kr[d4];
                a = fmaf(qv[d4].x, kvv.x, a);
                a = fmaf(qv[d4].y, kvv.y, a);
                a = fmaf(qv[d4].z, kvv.z, a);
                a = fmaf(qv[d4].w, kvv.w, a);
            }
            sc[kk] = a;
        }
        float rmax = sc[0];
        #pragma unroll
        for (int kk = 1; kk < 16; kk++) rmax = fmaxf(rmax, sc[kk]);
        rmax = fmaxf(rmax, __shfl_xor_sync(0xffffffffu, rmax, 1));
        rmax = fmaxf(rmax, __shfl_xor_sync(0xffffffffu, rmax, 2));

        const float mnew = fmaxf(mrun, rmax);
        const float scalef = __expf(mrun - mnew);
        float psum = 0.f;
        #pragma unroll
        for (int kk = 0; kk < 16; kk++) {
            const float p = __expf(sc[kk] - mnew);
            psum += p;
            Ss[q * SS_PAD + (kg + (kk << 2))] = p;
        }
        psum += __shfl_xor_sync(0xffffffffu, psum, 1);
        psum += __shfl_xor_sync(0xffffffffu, psum, 2);
        lrun = lrun * scalef + psum;
        mrun = mnew;
        if (kg == 0) sscale[q] = scalef;
        __syncthreads();

        #pragma unroll
        for (int i = 0; i < 4; i++) {
            const float s2 = sscale[qb + i];
            o[i].x *= s2; o[i].y *= s2; o[i].z *= s2; o[i].w *= s2;
        }
        #pragma unroll 8
        for (int k = 0; k < 64; k++) {
            const float4 vvv = *(const float4*)(&Vs[k * KV_PAD + c0]);
            #pragma unroll
            for (int i = 0; i < 4; i++) {
                const float p = Ss[(qb + i) * SS_PAD + k];
                o[i].x = fmaf(p, vvv.x, o[i].x);
                o[i].y = fmaf(p, vvv.y, o[i].y);
                o[i].z = fmaf(p, vvv.z, o[i].z);
                o[i].w = fmaf(p, vvv.w, o[i].w);
            }
        }
        __syncthreads();
    }

    if (kg == 0) sl[q] = lrun;
    __syncthreads();

    const int b = n >> 4;
    const int h = n & 15;
    #pragma unroll
    for (int i = 0; i < 4; i++) {
        const float inv = 1.0f / sl[qb + i];
        const int sgl = qt * 64 + qb + i;
        const size_t addr = ((size_t)sgl * BATCH + b) * EMB + h * HD + c0;
        float4 r, rhi, rlo;
        r.x = o[i].x * inv; r.y = o[i].y * inv;
        r.z = o[i].z * inv; r.w = o[i].w * inv;
        rhi.x = tf32_rna(r.x); rlo.x = tf32_rna(r.x - rhi.x);
        rhi.y = tf32_rna(r.y); rlo.y = tf32_rna(r.y - rhi.y);
        rhi.z = tf32_rna(r.z); rlo.z = tf32_rna(r.z - rhi.z);
        rhi.w = tf32_rna(r.w); rlo.w = tf32_rna(r.w - rhi.w);
        *(float4*)(&g_Chi[addr]) = rhi;
        *(float4*)(&g_Clo[addr]) = rlo;
    }
}

// ---------------------------------------------------------------------------
extern "C" void kernel_launch(void* const* d_in, const int* in_sizes, int n_in,
                              void* d_out, int out_size)
{
    const float* X  = (const float*)d_in[0];  // query [S,B,E]
    const float* Wq = (const float*)d_in[3];  // in_proj_w [3E,E]
    const float* bq = (const float*)d_in[4];  // in_proj_b [3E]
    const float* Wo = (const float*)d_in[5];  // out_proj_w [E,E]
    const float* bo = (const float*)d_in[6];  // out_proj_b [E]
    float* out = (float*)d_out;

    cudaFuncSetAttribute(attn_kernel,
                         cudaFuncAttributeMaxDynamicSharedMemorySize, ATTN_SMEM);
    cudaFuncSetAttribute(tc_gemm<0>,
                         cudaFuncAttributeMaxDynamicSharedMemorySize, G_SMEM);
    cudaFuncSetAttribute(tc_gemm<1>,
                         cudaFuncAttributeMaxDynamicSharedMemorySize, G_SMEM);

    float *xhi, *xlo, *wqhi, *wqlo, *wohi, *wolo, *chi, *clo;
    cudaGetSymbolAddress((void**)&xhi,  g_Xhi);
    cudaGetSymbolAddress((void**)&xlo,  g_Xlo);
    cudaGetSymbolAddress((void**)&wqhi, g_Wqhi);
    cudaGetSymbolAddress((void**)&wqlo, g_Wqlo);
    cudaGetSymbolAddress((void**)&wohi, g_Wohi);
    cudaGetSymbolAddress((void**)&wolo, g_Wolo);
    cudaGetSymbolAddress((void**)&chi,  g_Chi);
    cudaGetSymbolAddress((void**)&clo,  g_Clo);

    // 0) tf32 hi/lo splits of inputs and weights
    split_kernel<<<(MROWS*EMB/4 + 255)/256, 256>>>((const float4*)X, (float4*)xhi, (float4*)xlo, MROWS*EMB/4);
    split_kernel<<<(3*EMB*EMB/4 + 255)/256, 256>>>((const float4*)Wq, (float4*)wqhi, (float4*)wqlo, 3*EMB*EMB/4);
    split_kernel<<<(EMB*EMB/4 + 255)/256, 256>>>((const float4*)Wo, (float4*)wohi, (float4*)wolo, EMB*EMB/4);

    // 1) QKV projection (mma.sync tf32x3) + scatter into g_Q/g_K/g_V
    tc_gemm<0><<<dim3(3072/128, MROWS/128), 256, G_SMEM>>>(xhi, xlo, wqhi, wqlo, bq, nullptr);

    // 2) Attention (SIMT flash) — writes ctx hi/lo splits
    attn_kernel<<<dim3(SEQ/64, NHEADS_TOT), 256, ATTN_SMEM>>>();

    // 3) Output projection (mma.sync tf32x3)
    tc_gemm<1><<<dim3(1024/128, MROWS/128), 256, G_SMEM>>>(chi, clo, wohi, wolo, bo, out);
}

// round 8
// speedup vs baseline: 1.3971x; 1.1565x over previous
#include <cuda_runtime.h>
#include <math_constants.h>
#include <cstdint>

// Problem constants
#define SEQ   1024
#define BATCH 8
#define EMB   1024
#define NH    16
#define HD    64
#define MROWS (SEQ*BATCH)        // 8192
#define NHEADS_TOT (BATCH*NH)    // 128

// ---------------------------------------------------------------------------
// Scratch (device globals; allocation-free)
// ---------------------------------------------------------------------------
__device__ float g_Q[NHEADS_TOT * SEQ * HD];   // [n][s][d], pre-scaled by 1/8
__device__ float g_K[NHEADS_TOT * SEQ * HD];
__device__ float g_V[NHEADS_TOT * SEQ * HD];
__device__ float g_Xhi[MROWS * EMB];
__device__ float g_Xlo[MROWS * EMB];
__device__ float g_Wqhi[3 * EMB * EMB];
__device__ float g_Wqlo[3 * EMB * EMB];
__device__ float g_Wohi[EMB * EMB];
__device__ float g_Wolo[EMB * EMB];
__device__ float g_Chi[MROWS * EMB];           // ctx hi split, [s,b,e]
__device__ float g_Clo[MROWS * EMB];           // ctx lo split

// ---------------------------------------------------------------------------
// Helpers (sm_103 plain: mma.sync + cp.async only; NO tcgen05 anywhere)
// ---------------------------------------------------------------------------
__device__ __forceinline__ uint32_t smem_u32(const void* p) {
    uint32_t a;
    asm("{ .reg .u64 t; cvta.to.shared.u64 t, %1; cvt.u32.u64 %0, t; }"
        : "=r"(a) : "l"(p));
    return a;
}

__device__ __forceinline__ void cp16(uint32_t dst, const float* src) {
    asm volatile("cp.async.cg.shared.global [%0], [%1], 16;" :: "r"(dst), "l"(src));
}

__device__ __forceinline__ float tf32_rna(float x) {
    uint32_t u;
    asm("cvt.rna.tf32.f32 %0, %1;" : "=r"(u) : "f"(x));
    return __uint_as_float(u);
}

// D += A(16x8,row) * B(8x8,col) ; tf32 operands, f32 accum
__device__ __forceinline__ void mma8(float* c, const uint32_t* a, const uint32_t* b) {
    asm volatile(
        "mma.sync.aligned.m16n8k8.row.col.f32.tf32.tf32.f32 "
        "{%0,%1,%2,%3}, {%4,%5,%6,%7}, {%8,%9}, {%0,%1,%2,%3};"
        : "+f"(c[0]), "+f"(c[1]), "+f"(c[2]), "+f"(c[3])
        : "r"(a[0]), "r"(a[1]), "r"(a[2]), "r"(a[3]), "r"(b[0]), "r"(b[1]));
}

// ---------------------------------------------------------------------------
// Split kernel: x -> (hi = tf32(x), lo = tf32(x - hi))
// ---------------------------------------------------------------------------
__global__ __launch_bounds__(256) void split_kernel(
    const float4* __restrict__ src, float4* __restrict__ hi,
    float4* __restrict__ lo, int n4)
{
    int i = blockIdx.x * 256 + threadIdx.x;
    if (i >= n4) return;
    float4 x = src[i];
    float4 h, l;
    h.x = tf32_rna(x.x); l.x = tf32_rna(x.x - h.x);
    h.y = tf32_rna(x.y); l.y = tf32_rna(x.y - h.y);
    h.z = tf32_rna(x.z); l.z = tf32_rna(x.z - h.z);
    h.w = tf32_rna(x.w); l.w = tf32_rna(x.w - h.w);
    hi[i] = h; lo[i] = l;
}

// ---------------------------------------------------------------------------
// tf32x3 GEMM via mma.sync (unchanged from R7): C = A @ B^T + bias
// ---------------------------------------------------------------------------
#define BKF   32
#define ASTR  36
#define T_OFF (128*ASTR)
#define STAGE_F (4*T_OFF)
#define G_SMEM (2*STAGE_F*4)
#define NCHUNK (1024/BKF)

template<int MODE>
__global__ __launch_bounds__(256, 1)
void tc_gemm(const float* __restrict__ Ahi, const float* __restrict__ Alo,
             const float* __restrict__ Bhi, const float* __restrict__ Blo,
             const float* __restrict__ bias, float* __restrict__ Cout)
{
    extern __shared__ float sm[];
    const int tid  = threadIdx.x;
    const int wid  = tid >> 5;
    const int lane = tid & 31;
    const int m0 = blockIdx.y * 128;
    const int n0 = blockIdx.x * 128;
    const int warp_m = (wid & 1) * 64;
    const int warp_n = (wid >> 1) * 32;
    const int lr = lane >> 2;
    const int lc = lane & 3;

    float acc[4][4][4];
    #pragma unroll
    for (int mt = 0; mt < 4; mt++)
        #pragma unroll
        for (int nt = 0; nt < 4; nt++)
            #pragma unroll
            for (int r = 0; r < 4; r++) acc[mt][nt][r] = 0.0f;

    const uint32_t smb = smem_u32(sm);

    auto load_chunk = [&](int st, int k0) {
        const uint32_t sb = smb + (uint32_t)st * (STAGE_F * 4);
        #pragma unroll
        for (int i = 0; i < 4; i++) {
            const int idx = tid + i * 256;
            const int r = idx >> 3, q = idx & 7;
            const uint32_t o = (uint32_t)r * (ASTR * 4) + (uint32_t)q * 16;
            const size_t ga = (size_t)(m0 + r) * 1024 + k0 + q * 4;
            const size_t gb = (size_t)(n0 + r) * 1024 + k0 + q * 4;
            cp16(sb + 0 * (T_OFF * 4) + o, Ahi + ga);
            cp16(sb + 1 * (T_OFF * 4) + o, Alo + ga);
            cp16(sb + 2 * (T_OFF * 4) + o, Bhi + gb);
            cp16(sb + 3 * (T_OFF * 4) + o, Blo + gb);
        }
        asm volatile("cp.async.commit_group;" ::: "memory");
    };

    load_chunk(0, 0);
    load_chunk(1, BKF);

    for (int c = 0; c < NCHUNK; c++) {
        if (c < NCHUNK - 1) asm volatile("cp.async.wait_group 1;" ::: "memory");
        else                asm volatile("cp.async.wait_group 0;" ::: "memory");
        __syncthreads();

        const float* As_hi = sm + (c & 1) * STAGE_F;
        const float* As_lo = As_hi + T_OFF;
        const float* Bs_hi = As_hi + 2 * T_OFF;
        const float* Bs_lo = As_hi + 3 * T_OFF;

        #pragma unroll
        for (int kk = 0; kk < BKF; kk += 8) {
            uint32_t ah[4][4], al[4][4], bh[4][2], bl[4][2];
            #pragma unroll
            for (int mt = 0; mt < 4; mt++) {
                const int r = warp_m + mt * 16 + lr;
                const float* p  = As_hi + r * ASTR + kk + lc;
                const float* pl = As_lo + r * ASTR + kk + lc;
                ah[mt][0] = __float_as_uint(p[0]);
                ah[mt][1] = __float_as_uint(p[8 * ASTR]);
                ah[mt][2] = __float_as_uint(p[4]);
                ah[mt][3] = __float_as_uint(p[8 * ASTR + 4]);
                al[mt][0] = __float_as_uint(pl[0]);
                al[mt][1] = __float_as_uint(pl[8 * ASTR]);
                al[mt][2] = __float_as_uint(pl[4]);
                al[mt][3] = __float_as_uint(pl[8 * ASTR + 4]);
            }
            #pragma unroll
            for (int nt = 0; nt < 4; nt++) {
                const int r = warp_n + nt * 8 + lr;
                const float* p  = Bs_hi + r * ASTR + kk + lc;
                const float* pl = Bs_lo + r * ASTR + kk + lc;
                bh[nt][0] = __float_as_uint(p[0]);
                bh[nt][1] = __float_as_uint(p[4]);
                bl[nt][0] = __float_as_uint(pl[0]);
                bl[nt][1] = __float_as_uint(pl[4]);
            }
            #pragma unroll
            for (int mt = 0; mt < 4; mt++)
                #pragma unroll
                for (int nt = 0; nt < 4; nt++) {
                    mma8(acc[mt][nt], ah[mt], bh[nt]);
                    mma8(acc[mt][nt], ah[mt], bl[nt]);
                    mma8(acc[mt][nt], al[mt], bh[nt]);
                }
        }
        __syncthreads();
        if (c + 2 < NCHUNK) load_chunk(c & 1, (c + 2) * BKF);
    }

    #pragma unroll
    for (int mt = 0; mt < 4; mt++) {
        #pragma unroll
        for (int nt = 0; nt < 4; nt++) {
            const int gm = m0 + warp_m + mt * 16 + lr;
            const int gn = n0 + warp_n + nt * 8 + lc * 2;
            #pragma unroll
            for (int half = 0; half < 2; half++) {
                const int m = gm + half * 8;
                const float v0 = acc[mt][nt][half * 2 + 0] + __ldg(&bias[gn]);
                const float v1 = acc[mt][nt][half * 2 + 1] + __ldg(&bias[gn + 1]);
                if (MODE == 0) {
                    const int s = m >> 3;
                    const int b = m & 7;
                    const int h = gn / 192;
                    const int cc = gn - h * 192;
                    const int w = cc >> 6;
                    const int d = cc & 63;
                    const size_t idx = ((size_t)(b * NH + h) * SEQ + s) * HD + d;
                    if (w == 0)      { g_Q[idx] = v0 * 0.125f; g_Q[idx + 1] = v1 * 0.125f; }
                    else if (w == 1) { g_K[idx] = v0;          g_K[idx + 1] = v1; }
                    else             { g_V[idx] = v0;          g_V[idx + 1] = v1; }
                } else {
                    Cout[(size_t)m * 1024 + gn]     = v0;
                    Cout[(size_t)m * 1024 + gn + 1] = v1;
                }
            }
        }
    }
}

// ---------------------------------------------------------------------------
// Tensor-core flash attention. Block = (qt 64 queries, head n), 256 threads.
// 8 warps: warp_m=(wid&1)*32, warp_n=(wid>>1)*16; warp tile 32x16 of S/O.
// QK^T: tf32x3; P: exact hi+lo split; V: hi/lo split; PV: 3 terms.
// Smem hi/lo interleaved, stride 136 floats (mod 32 = 8 -> conflict-free v2).
// ---------------------------------------------------------------------------
#define XSTR 136
#define VSTRK 136
#define ATTN2_SMEM (35584 * 4)   // floats: 3*8704(Q,K,P) + 8704(V) + 512 + 256

__global__ __launch_bounds__(256, 1) void attn_tc_kernel()
{
    extern __shared__ float sh[];
    float* Qd   = sh;                    // [64][136]  q-major, 2d+{hi,lo}
    float* Kd   = Qd + 64 * XSTR;        // [64][136]  k-major, 2d+{hi,lo}
    float* Vd   = Kd + 64 * XSTR;        // [64][136]  k-major, 2d+{hi,lo}
    float* Pd   = Vd + 64 * VSTRK;       // [64][136]  q-major, 2k+{hi,lo}
    float* wmax = Pd + 64 * XSTR;        // [4][64]
    float* wsum = wmax + 256;            // [4][64]
    float* mrun = wsum + 256;            // [64]
    float* lrun = mrun + 64;             // [64]
    float* ssc  = lrun + 64;             // [64]
    float* mnew = ssc + 64;              // [64]

    const int tid  = threadIdx.x;
    const int wid  = tid >> 5;
    const int lane = tid & 31;
    const int lr = lane >> 2;
    const int lc = lane & 3;
    const int n  = blockIdx.y;           // head (b*16+h)
    const int qt = blockIdx.x;
    const int warp_m = (wid & 1) * 32;
    const int warp_n = (wid >> 1) * 16;
    const int wcol   = wid >> 1;

    const float* Qg = g_Q + ((size_t)n * SEQ + qt * 64) * HD;
    const float* Kg = g_K + (size_t)n * SEQ * HD;
    const float* Vg = g_V + (size_t)n * SEQ * HD;

    // Stage Q (split, interleaved)
    for (int i = tid; i < 64 * 16; i += 256) {
        const int r = i >> 4, c4 = (i & 15) << 2;
        float4 v = *(const float4*)(Qg + r * HD + c4);
        float hx = tf32_rna(v.x), hy = tf32_rna(v.y);
        float hz = tf32_rna(v.z), hw = tf32_rna(v.w);
        float* q = &Qd[r * XSTR + c4 * 2];
        *(float4*)(q)     = make_float4(hx, tf32_rna(v.x - hx), hy, tf32_rna(v.y - hy));
        *(float4*)(q + 4) = make_float4(hz, tf32_rna(v.z - hz), hw, tf32_rna(v.w - hw));
    }
    if (tid < 64) { mrun[tid] = -CUDART_INF_F; lrun[tid] = 0.f; }
    __syncthreads();

    // Hoist Q fragments to registers (tile-invariant): qh/ql [mt][ks][4]
    uint32_t qh[2][8][4], ql[2][8][4];
    #pragma unroll
    for (int mt = 0; mt < 2; mt++) {
        const float* base = &Qd[(warp_m + mt * 16) * XSTR];
        #pragma unroll
        for (int ks = 0; ks < 8; ks++) {
            const int k2 = 2 * (ks * 8 + lc);
            uint2 f0 = *(const uint2*)&base[lr * XSTR + k2];
            uint2 f1 = *(const uint2*)&base[(lr + 8) * XSTR + k2];
            uint2 f2 = *(const uint2*)&base[lr * XSTR + k2 + 8];
            uint2 f3 = *(const uint2*)&base[(lr + 8) * XSTR + k2 + 8];
            qh[mt][ks][0] = f0.x; ql[mt][ks][0] = f0.y;
            qh[mt][ks][1] = f1.x; ql[mt][ks][1] = f1.y;
            qh[mt][ks][2] = f2.x; ql[mt][ks][2] = f2.y;
            qh[mt][ks][3] = f3.x; ql[mt][ks][3] = f3.y;
        }
    }

    float o[2][2][4];
    #pragma unroll
    for (int mt = 0; mt < 2; mt++)
        #pragma unroll
        for (int nt = 0; nt < 2; nt++)
            #pragma unroll
            for (int r = 0; r < 4; r++) o[mt][nt][r] = 0.f;

    for (int kt = 0; kt < 16; kt++) {
        __syncthreads();   // prev-iter readers of Kd/Vd/Pd done
        // Stage K,V (split, interleaved)
        for (int i = tid; i < 64 * 16; i += 256) {
            const int r = i >> 4, c4 = (i & 15) << 2;
            const size_t go = (size_t)(kt * 64 + r) * HD + c4;
            float4 kv = *(const float4*)(Kg + go);
            float4 vv = *(const float4*)(Vg + go);
            float hx, hy, hz, hw;
            hx = tf32_rna(kv.x); hy = tf32_rna(kv.y);
            hz = tf32_rna(kv.z); hw = tf32_rna(kv.w);
            float* kd = &Kd[r * XSTR + c4 * 2];
            *(float4*)(kd)     = make_float4(hx, tf32_rna(kv.x - hx), hy, tf32_rna(kv.y - hy));
            *(float4*)(kd + 4) = make_float4(hz, tf32_rna(kv.z - hz), hw, tf32_rna(kv.w - hw));
            hx = tf32_rna(vv.x); hy = tf32_rna(vv.y);
            hz = tf32_rna(vv.z); hw = tf32_rna(vv.w);
            float* vd = &Vd[r * VSTRK + c4 * 2];
            *(float4*)(vd)     = make_float4(hx, tf32_rna(vv.x - hx), hy, tf32_rna(vv.y - hy));
            *(float4*)(vd + 4) = make_float4(hz, tf32_rna(vv.z - hz), hw, tf32_rna(vv.w - hw));
        }
        __syncthreads();

        // ---- S = Q @ K^T (tf32x3) ----
        float s[2][2][4];
        #pragma unroll
        for (int mt = 0; mt < 2; mt++)
            #pragma unroll
            for (int nt = 0; nt < 2; nt++)
                #pragma unroll
                for (int r = 0; r < 4; r++) s[mt][nt][r] = 0.f;

        #pragma unroll
        for (int ks = 0; ks < 8; ks++) {
            uint32_t bh[2][2], bl[2][2];
            #pragma unroll
            for (int nt = 0; nt < 2; nt++) {
                const float* kb = &Kd[(warp_n + nt * 8 + lr) * XSTR + 2 * (ks * 8 + lc)];
                uint2 f0 = *(const uint2*)kb;
                uint2 f1 = *(const uint2*)(kb + 8);
                bh[nt][0] = f0.x; bl[nt][0] = f0.y;
                bh[nt][1] = f1.x; bl[nt][1] = f1.y;
            }
            #pragma unroll
            for (int mt = 0; mt < 2; mt++)
                #pragma unroll
                for (int nt = 0; nt < 2; nt++) {
                    mma8(s[mt][nt], qh[mt][ks], bh[nt]);
                    mma8(s[mt][nt], qh[mt][ks], bl[nt]);
                    mma8(s[mt][nt], ql[mt][ks], bh[nt]);
                }
        }

        // ---- row max partials ----
        #pragma unroll
        for (int mt = 0; mt < 2; mt++) {
            float m0 = fmaxf(fmaxf(s[mt][0][0], s[mt][0][1]), fmaxf(s[mt][1][0], s[mt][1][1]));
            float m1 = fmaxf(fmaxf(s[mt][0][2], s[mt][0][3]), fmaxf(s[mt][1][2], s[mt][1][3]));
            m0 = fmaxf(m0, __shfl_xor_sync(0xffffffffu, m0, 1));
            m0 = fmaxf(m0, __shfl_xor_sync(0xffffffffu, m0, 2));
            m1 = fmaxf(m1, __shfl_xor_sync(0xffffffffu, m1, 1));
            m1 = fmaxf(m1, __shfl_xor_sync(0xffffffffu, m1, 2));
            if (lc == 0) {
                wmax[wcol * 64 + warp_m + mt * 16 + lr]     = m0;
                wmax[wcol * 64 + warp_m + mt * 16 + lr + 8] = m1;
            }
        }
        __syncthreads();
        if (tid < 64) {
            const float mo = mrun[tid];
            float mn = fmaxf(fmaxf(wmax[tid], wmax[64 + tid]),
                             fmaxf(wmax[128 + tid], wmax[192 + tid]));
            mn = fmaxf(mn, mo);
            mnew[tid] = mn;
            ssc[tid]  = __expf(mo - mn);
            mrun[tid] = mn;
        }
        __syncthreads();

        // ---- P = exp(S - mnew), sums, store hi/lo, rescale O ----
        #pragma unroll
        for (int mt = 0; mt < 2; mt++) {
            const int r0 = warp_m + mt * 16 + lr;
            const float mn0 = mnew[r0], mn1 = mnew[r0 + 8];
            float ps0 = 0.f, ps1 = 0.f;
            #pragma unroll
            for (int nt = 0; nt < 2; nt++) {
                const float p0 = __expf(s[mt][nt][0] - mn0);
                const float p1 = __expf(s[mt][nt][1] - mn0);
                const float p2 = __expf(s[mt][nt][2] - mn1);
                const float p3 = __expf(s[mt][nt][3] - mn1);
                ps0 += p0 + p1; ps1 += p2 + p3;
                const float h0 = tf32_rna(p0), h1 = tf32_rna(p1);
                const float h2 = tf32_rna(p2), h3 = tf32_rna(p3);
                const int cbase = 2 * (warp_n + nt * 8 + 2 * lc);
                *(float4*)&Pd[r0 * XSTR + cbase] =
                    make_float4(h0, tf32_rna(p0 - h0), h1, tf32_rna(p1 - h1));
                *(float4*)&Pd[(r0 + 8) * XSTR + cbase] =
                    make_float4(h2, tf32_rna(p2 - h2), h3, tf32_rna(p3 - h3));
            }
            ps0 += __shfl_xor_sync(0xffffffffu, ps0, 1);
            ps0 += __shfl_xor_sync(0xffffffffu, ps0, 2);
            ps1 += __shfl_xor_sync(0xffffffffu, ps1, 1);
            ps1 += __shfl_xor_sync(0xffffffffu, ps1, 2);
            if (lc == 0) {
                wsum[wcol * 64 + r0]     = ps0;
                wsum[wcol * 64 + r0 + 8] = ps1;
            }
            const float sc0 = ssc[r0], sc1 = ssc[r0 + 8];
            #pragma unroll
            for (int nt = 0; nt < 2; nt++) {
                o[mt][nt][0] *= sc0; o[mt][nt][1] *= sc0;
                o[mt][nt][2] *= sc1; o[mt][nt][3] *= sc1;
            }
        }
        __syncthreads();
        if (tid < 64)
            lrun[tid] = lrun[tid] * ssc[tid]
                      + (wsum[tid] + wsum[64 + tid] + wsum[128 + tid] + wsum[192 + tid]);

        // ---- O += P @ V (P exact hi/lo, V hi/lo, 3 terms) ----
        #pragma unroll
        for (int ks = 0; ks < 8; ks++) {
            uint32_t vh[2][2], vl[2][2];
            #pragma unroll
            for (int nt = 0; nt < 2; nt++) {
                const float* vb = &Vd[(ks * 8 + lc) * VSTRK + 2 * (warp_n + nt * 8 + lr)];
                uint2 f0 = *(const uint2*)vb;
                uint2 f1 = *(const uint2*)(vb + 4 * VSTRK);
                vh[nt][0] = f0.x; vl[nt][0] = f0.y;
                vh[nt][1] = f1.x; vl[nt][1] = f1.y;
            }
            #pragma unroll
            for (int mt = 0; mt < 2; mt++) {
                const float* pb = &Pd[(warp_m + mt * 16) * XSTR];
                const int k2 = 2 * (ks * 8 + lc);
                uint2 f0 = *(const uint2*)&pb[lr * XSTR + k2];
                uint2 f1 = *(const uint2*)&pb[(lr + 8) * XSTR + k2];
                uint2 f2 = *(const uint2*)&pb[lr * XSTR + k2 + 8];
                uint2 f3 = *(const uint2*)&pb[(lr + 8) * XSTR + k2 + 8];
                uint32_t ph[4] = {f0.x, f1.x, f2.x, f3.x};
                uint32_t pl[4] = {f0.y, f1.y, f2.y, f3.y};
                #pragma unroll
                for (int nt = 0; nt < 2; nt++) {
                    mma8(o[mt][nt], ph, vh[nt]);
                    mma8(o[mt][nt], ph, vl[nt]);
                    mma8(o[mt][nt], pl, vh[nt]);
                }
            }
        }
    }

    __syncthreads();
    // Normalize and store ctx hi/lo splits to [s,b,e]
    const int b = n >> 4;
    const int h = n & 15;
    #pragma unroll
    for (int mt = 0; mt < 2; mt++) {
        const int r0 = warp_m + mt * 16 + lr;
        const float li0 = 1.0f / lrun[r0];
        const float li1 = 1.0f / lrun[r0 + 8];
        #pragma unroll
        for (int nt = 0; nt < 2; nt++) {
            const int d = warp_n + nt * 8 + 2 * lc;
            #pragma unroll
            for (int half = 0; half < 2; half++) {
                const int row = r0 + half * 8;
                const float li = half ? li1 : li0;
                const float v0 = o[mt][nt][half * 2 + 0] * li;
                const float v1 = o[mt][nt][half * 2 + 1] * li;
                const size_t addr = ((size_t)(qt * 64 + row) * BATCH + b) * EMB + h * HD + d;
                const float h0 = tf32_rna(v0), h1 = tf32_rna(v1);
                *(float2*)&g_Chi[addr] = make_float2(h0, h1);
                *(float2*)&g_Clo[addr] = make_float2(tf32_rna(v0 - h0), tf32_rna(v1 - h1));
            }
        }
    }
}

// ---------------------------------------------------------------------------
extern "C" void kernel_launch(void* const* d_in, const int* in_sizes, int n_in,
                              void* d_out, int out_size)
{
    const float* X  = (const float*)d_in[0];  // query [S,B,E]
    const float* Wq = (const float*)d_in[3];  // in_proj_w [3E,E]
    const float* bq = (const float*)d_in[4];  // in_proj_b [3E]
    const float* Wo = (const float*)d_in[5];  // out_proj_w [E,E]
    const float* bo = (const float*)d_in[6];  // out_proj_b [E]
    float* out = (float*)d_out;

    cudaFuncSetAttribute(attn_tc_kernel,
                         cudaFuncAttributeMaxDynamicSharedMemorySize, ATTN2_SMEM);
    cudaFuncSetAttribute(tc_gemm<0>,
                         cudaFuncAttributeMaxDynamicSharedMemorySize, G_SMEM);
    cudaFuncSetAttribute(tc_gemm<1>,
                         cudaFuncAttributeMaxDynamicSharedMemorySize, G_SMEM);

    float *xhi, *xlo, *wqhi, *wqlo, *wohi, *wolo, *chi, *clo;
    cudaGetSymbolAddress((void**)&xhi,  g_Xhi);
    cudaGetSymbolAddress((void**)&xlo,  g_Xlo);
    cudaGetSymbolAddress((void**)&wqhi, g_Wqhi);
    cudaGetSymbolAddress((void**)&wqlo, g_Wqlo);
    cudaGetSymbolAddress((void**)&wohi, g_Wohi);
    cudaGetSymbolAddress((void**)&wolo, g_Wolo);
    cudaGetSymbolAddress((void**)&chi,  g_Chi);
    cudaGetSymbolAddress((void**)&clo,  g_Clo);

    // 0) tf32 hi/lo splits of inputs and weights
    split_kernel<<<(MROWS*EMB/4 + 255)/256, 256>>>((const float4*)X, (float4*)xhi, (float4*)xlo, MROWS*EMB/4);
    split_kernel<<<(3*EMB*EMB/4 + 255)/256, 256>>>((const float4*)Wq, (float4*)wqhi, (float4*)wqlo, 3*EMB*EMB/4);
    split_kernel<<<(EMB*EMB/4 + 255)/256, 256>>>((const float4*)Wo, (float4*)wohi, (float4*)wolo, EMB*EMB/4);

    // 1) QKV projection (mma.sync tf32x3) + scatter into g_Q/g_K/g_V
    tc_gemm<0><<<dim3(3072/128, MROWS/128), 256, G_SMEM>>>(xhi, xlo, wqhi, wqlo, bq, nullptr);

    // 2) Tensor-core flash attention — writes ctx hi/lo splits
    attn_tc_kernel<<<dim3(SEQ/64, NHEADS_TOT), 256, ATTN2_SMEM>>>();

    // 3) Output projection (mma.sync tf32x3)
    tc_gemm<1><<<dim3(1024/128, MROWS/128), 256, G_SMEM>>>(chi, clo, wohi, wolo, bo, out);
}